// round 2
// baseline (speedup 1.0000x reference)
#include <cuda_runtime.h>

#define NN 50000
#define NE 600000
#define HID 128

// ---- scratch (static device allocations; no cudaMalloc allowed) ----
__device__ int   g_ni[NE];
__device__ int   g_ei[NE];
__device__ int   g_dcnt[NN];
__device__ int   g_bcnt[NN];
__device__ float g_dinv[NN];
__device__ float g_binv[NN];
__device__ float g_xw[NN * HID];
__device__ float g_m[NN * HID];
__device__ float g_h[NN * HID];
__device__ int   g_is_i32;   // 1 if hyper_edge_index buffer is int32, 0 if int64

// ---- dtype probe: if ANY of the first 4096 int64 reads is out of [0, NN),
//      the buffer must be int32 (two packed indices look huge as int64). ----
__global__ void k_zero_flag() { if (threadIdx.x == 0 && blockIdx.x == 0) g_is_i32 = 0; }

__global__ void k_detect(const long long* __restrict__ hei64) {
    int i = blockIdx.x * blockDim.x + threadIdx.x;
    if (i < 4096) {
        long long v = hei64[i];
        if (v < 0 || v >= NN) atomicExch(&g_is_i32, 1);
    }
}

// ---- degree / index prep ----
__global__ void k_zero_counts() {
    int i = blockIdx.x * blockDim.x + threadIdx.x;
    if (i < NN) { g_dcnt[i] = 0; g_bcnt[i] = 0; }
}

__global__ void k_idx_deg(const void* __restrict__ hei) {
    int i = blockIdx.x * blockDim.x + threadIdx.x;
    if (i >= NE) return;
    int n, e;
    if (g_is_i32) {
        const int* h32 = (const int*)hei;
        n = h32[i];
        e = h32[NE + i];
    } else {
        const long long* h64 = (const long long*)hei;
        n = (int)h64[i];
        e = (int)h64[NE + i];
    }
    // bounds guard: never fault, garbage would show as rel_err instead
    if (n < 0 || n >= NN) n = 0;
    if (e < 0 || e >= NN) e = 0;
    g_ni[i] = n;
    g_ei[i] = e;
    atomicAdd(&g_dcnt[n], 1);
    atomicAdd(&g_bcnt[e], 1);
}

__global__ void k_inv() {
    int i = blockIdx.x * blockDim.x + threadIdx.x;
    if (i < NN) {
        int d = g_dcnt[i];
        int b = g_bcnt[i];
        g_dinv[i] = d > 0 ? 1.0f / (float)d : 0.0f;
        g_binv[i] = b > 0 ? 1.0f / (float)b : 0.0f;
    }
}

// ---- GEMM: C[M,128] = A[M,128] @ W[128,128], fp32, 128x128 block tile,
//      8x8 per thread, A staged transposed in smem (pad 129 -> conflict-free) ----
__global__ __launch_bounds__(256) void k_gemm(const float* __restrict__ A,
                                              const float* __restrict__ W,
                                              float* __restrict__ C, int M) {
    __shared__ float sAT[32][129];  // [k][row]
    __shared__ float sW[32][128];   // [k][col]
    int tid = threadIdx.x;
    int tx = tid & 15;          // col group
    int ty = tid >> 4;          // row group
    int rb = blockIdx.x * 128;

    int lr = tid >> 3;          // 0..31  (row within 32-row load slab)
    int kq = tid & 7;           // 0..7   (float4 index along k)

    float acc[8][8];
#pragma unroll
    for (int i = 0; i < 8; i++)
#pragma unroll
        for (int j = 0; j < 8; j++) acc[i][j] = 0.0f;

    for (int kk = 0; kk < 128; kk += 32) {
        __syncthreads();
        // load A chunk transposed: sAT[k][r] = A[rb+r][kk+k]
#pragma unroll
        for (int t = 0; t < 4; t++) {
            int r = lr + t * 32;
            float4 v = make_float4(0.f, 0.f, 0.f, 0.f);
            if (rb + r < M)
                v = *(const float4*)(A + (size_t)(rb + r) * HID + kk + kq * 4);
            sAT[kq * 4 + 0][r] = v.x;
            sAT[kq * 4 + 1][r] = v.y;
            sAT[kq * 4 + 2][r] = v.z;
            sAT[kq * 4 + 3][r] = v.w;
        }
        // load W chunk: sW[k][c] = W[kk+k][c]
#pragma unroll
        for (int t = 0; t < 4; t++) {
            int i4 = tid + t * 256;     // 0..1023 float4 slots
            int k = i4 >> 5, c4 = i4 & 31;
            *(float4*)(&sW[k][c4 * 4]) =
                *(const float4*)(W + (size_t)(kk + k) * HID + c4 * 4);
        }
        __syncthreads();

#pragma unroll
        for (int k = 0; k < 32; k++) {
            float a[8], b[8];
#pragma unroll
            for (int i = 0; i < 8; i++) a[i] = sAT[k][ty * 8 + i];
            *(float4*)(b)     = *(const float4*)(&sW[k][tx * 8]);
            *(float4*)(b + 4) = *(const float4*)(&sW[k][tx * 8 + 4]);
#pragma unroll
            for (int i = 0; i < 8; i++)
#pragma unroll
                for (int j = 0; j < 8; j++) acc[i][j] += a[i] * b[j];
        }
    }

#pragma unroll
    for (int i = 0; i < 8; i++) {
        int r = rb + ty * 8 + i;
        if (r < M) {
            *(float4*)(C + (size_t)r * HID + tx * 8)     = *(float4*)(&acc[i][0]);
            *(float4*)(C + (size_t)r * HID + tx * 8 + 4) = *(float4*)(&acc[i][4]);
        }
    }
}

// ---- scatter node->edge: dst[ei[w]] += src[ni[w]]  (one warp per entry) ----
__global__ void k_scatter_ne(const float* __restrict__ src, float* __restrict__ dst) {
    int g = blockIdx.x * blockDim.x + threadIdx.x;
    int w = g >> 5;
    int lane = g & 31;
    if (w >= NE) return;
    int n = g_ni[w];
    int e = g_ei[w];
    float4 v = ((const float4*)src)[(size_t)n * 32 + lane];
    float* p = dst + (size_t)e * HID + lane * 4;
    asm volatile("red.global.add.v4.f32 [%0], {%1,%2,%3,%4};"
                 :: "l"(p), "f"(v.x), "f"(v.y), "f"(v.z), "f"(v.w)
                 : "memory");
}

// ---- scatter edge->node with fused B^{-1}: dst[ni[w]] += src[ei[w]] * binv[ei[w]] ----
__global__ void k_scatter_en(const float* __restrict__ src, float* __restrict__ dst) {
    int g = blockIdx.x * blockDim.x + threadIdx.x;
    int w = g >> 5;
    int lane = g & 31;
    if (w >= NE) return;
    int n = g_ni[w];
    int e = g_ei[w];
    float s = g_binv[e];
    float4 v = ((const float4*)src)[(size_t)e * 32 + lane];
    v.x *= s; v.y *= s; v.z *= s; v.w *= s;
    float* p = dst + (size_t)n * HID + lane * 4;
    asm volatile("red.global.add.v4.f32 [%0], {%1,%2,%3,%4};"
                 :: "l"(p), "f"(v.x), "f"(v.y), "f"(v.z), "f"(v.w)
                 : "memory");
}

// ---- epilogue 1: g_h = prelu(g_h * dinv[row] + b1[col]) ----
__global__ void k_epi1(const float* __restrict__ b1, const float* __restrict__ pa) {
    int i = blockIdx.x * blockDim.x + threadIdx.x;  // float4 index
    if (i >= NN * 32) return;
    int row = i >> 5, c4 = i & 31;
    float d = g_dinv[row];
    float a = pa[0];
    float4 v = ((float4*)g_h)[i];
    float4 b = ((const float4*)b1)[c4];
    v.x = v.x * d + b.x; v.x = v.x >= 0.f ? v.x : a * v.x;
    v.y = v.y * d + b.y; v.y = v.y >= 0.f ? v.y : a * v.y;
    v.z = v.z * d + b.z; v.z = v.z >= 0.f ? v.z : a * v.z;
    v.w = v.w * d + b.w; v.w = v.w >= 0.f ? v.w : a * v.w;
    ((float4*)g_h)[i] = v;
}

// ---- epilogue 2: out = prelu(out * dinv[row] + b2[col] + x)  (in place on d_out) ----
__global__ void k_epi2(const float* __restrict__ x, const float* __restrict__ b2,
                       const float* __restrict__ pa, float* __restrict__ out) {
    int i = blockIdx.x * blockDim.x + threadIdx.x;  // float4 index
    if (i >= NN * 32) return;
    int row = i >> 5, c4 = i & 31;
    float d = g_dinv[row];
    float a = pa[0];
    float4 v = ((float4*)out)[i];
    float4 b = ((const float4*)b2)[c4];
    float4 xv = ((const float4*)x)[i];
    v.x = v.x * d + b.x + xv.x; v.x = v.x >= 0.f ? v.x : a * v.x;
    v.y = v.y * d + b.y + xv.y; v.y = v.y >= 0.f ? v.y : a * v.y;
    v.z = v.z * d + b.z + xv.z; v.z = v.z >= 0.f ? v.z : a * v.z;
    v.w = v.w * d + b.w + xv.w; v.w = v.w >= 0.f ? v.w : a * v.w;
    ((float4*)out)[i] = v;
}

extern "C" void kernel_launch(void* const* d_in, const int* in_sizes, int n_in,
                              void* d_out, int out_size) {
    (void)in_sizes; (void)n_in; (void)out_size;
    const float* x   = (const float*)d_in[0];
    const void*  hei = d_in[1];
    const float* W1  = (const float*)d_in[2];
    const float* b1  = (const float*)d_in[3];
    const float* W2  = (const float*)d_in[4];
    const float* b2  = (const float*)d_in[5];
    const float* pa  = (const float*)d_in[6];
    float* out = (float*)d_out;

    float *pxw, *pm, *ph;
    cudaGetSymbolAddress((void**)&pxw, g_xw);
    cudaGetSymbolAddress((void**)&pm,  g_m);
    cudaGetSymbolAddress((void**)&ph,  g_h);

    const int SC_BLOCKS = (NE * 32) / 256;       // 75000
    const int EL_BLOCKS = (NN * 32 + 255) / 256; // elementwise float4 grid

    // dtype probe + degrees + int32 indices
    k_zero_flag<<<1, 32>>>();
    k_detect<<<16, 256>>>((const long long*)hei);
    k_zero_counts<<<(NN + 255) / 256, 256>>>();
    k_idx_deg<<<(NE + 255) / 256, 256>>>(hei);
    k_inv<<<(NN + 255) / 256, 256>>>();

    // ---- layer 1 ----
    k_gemm<<<(NN + 127) / 128, 256>>>(x, W1, pxw, NN);
    cudaMemsetAsync(pm, 0, sizeof(float) * NN * HID, 0);
    k_scatter_ne<<<SC_BLOCKS, 256>>>(pxw, pm);
    cudaMemsetAsync(ph, 0, sizeof(float) * NN * HID, 0);
    k_scatter_en<<<SC_BLOCKS, 256>>>(pm, ph);
    k_epi1<<<EL_BLOCKS, 256>>>(b1, pa);

    // ---- layer 2 ----
    k_gemm<<<(NN + 127) / 128, 256>>>(ph, W2, pxw, NN);
    cudaMemsetAsync(pm, 0, sizeof(float) * NN * HID, 0);
    k_scatter_ne<<<SC_BLOCKS, 256>>>(pxw, pm);
    cudaMemsetAsync(out, 0, sizeof(float) * NN * HID, 0);
    k_scatter_en<<<SC_BLOCKS, 256>>>(pm, out);
    k_epi2<<<EL_BLOCKS, 256>>>(x, b2, pa, out);
}

// round 3
// speedup vs baseline: 1.6666x; 1.6666x over previous
#include <cuda_runtime.h>

#define NN 50000
#define NE 600000
#define HID 128

#define SCAN_BS 256
#define SCAN_VT 8
#define SCAN_ELEMS (SCAN_BS * SCAN_VT)              // 2048
#define SCAN_NBLK ((2 * NN + SCAN_ELEMS - 1) / SCAN_ELEMS)  // 49

// ---- scratch (static device allocations; no cudaMalloc allowed) ----
__device__ int   g_ni[NE];
__device__ int   g_ei[NE];
__device__ int   g_cnt[2 * NN];       // [0,NN): node degree D; [NN,2NN): hedge degree B
__device__ int   g_offs[2 * NN + 1];  // combined exclusive offsets; [2NN] = 2*NE
__device__ int   g_bsum[SCAN_NBLK];
__device__ int   g_csr[2 * NE];       // node rows hold edge ids; edge rows hold node ids
__device__ float g_dinv[NN];
__device__ float g_binv[NN];
__device__ float g_xw[NN * HID];
__device__ float g_m[NN * HID];
__device__ float g_h[NN * HID];
__device__ int   g_is_i32;

// ---- dtype probe ----
__global__ void k_zero_flag() { if (threadIdx.x == 0 && blockIdx.x == 0) g_is_i32 = 0; }

__global__ void k_detect(const long long* __restrict__ hei64) {
    int i = blockIdx.x * blockDim.x + threadIdx.x;
    if (i < 4096) {
        long long v = hei64[i];
        if (v < 0 || v >= NN) atomicExch(&g_is_i32, 1);
    }
}

// ---- counts ----
__global__ void k_zero_counts() {
    int i = blockIdx.x * blockDim.x + threadIdx.x;
    if (i < 2 * NN) g_cnt[i] = 0;
}

__global__ void k_idx_deg(const void* __restrict__ hei) {
    int i = blockIdx.x * blockDim.x + threadIdx.x;
    if (i >= NE) return;
    int n, e;
    if (g_is_i32) {
        const int* h32 = (const int*)hei;
        n = h32[i];
        e = h32[NE + i];
    } else {
        const long long* h64 = (const long long*)hei;
        n = (int)h64[i];
        e = (int)h64[NE + i];
    }
    if (n < 0 || n >= NN) n = 0;
    if (e < 0 || e >= NN) e = 0;
    g_ni[i] = n;
    g_ei[i] = e;
    atomicAdd(&g_cnt[n], 1);
    atomicAdd(&g_cnt[NN + e], 1);
}

// ---- exclusive scan over g_cnt[0 : 2NN] -> g_offs ----
__global__ __launch_bounds__(SCAN_BS) void k_scanA() {
    __shared__ int s[SCAN_BS];
    int blk = blockIdx.x, tid = threadIdx.x;
    int base = blk * SCAN_ELEMS + tid * SCAN_VT;
    int v[SCAN_VT];
    int sum = 0;
#pragma unroll
    for (int t = 0; t < SCAN_VT; t++) {
        v[t] = (base + t < 2 * NN) ? g_cnt[base + t] : 0;
        sum += v[t];
    }
    s[tid] = sum;
    __syncthreads();
    for (int off = 1; off < SCAN_BS; off <<= 1) {
        int t = (tid >= off) ? s[tid - off] : 0;
        __syncthreads();
        s[tid] += t;
        __syncthreads();
    }
    if (tid == SCAN_BS - 1) g_bsum[blk] = s[tid];
    int run = s[tid] - sum;  // exclusive prefix of this thread within block
#pragma unroll
    for (int t = 0; t < SCAN_VT; t++) {
        if (base + t < 2 * NN) g_offs[base + t] = run;
        run += v[t];
    }
}

__global__ void k_scanB() {
    if (threadIdx.x == 0 && blockIdx.x == 0) {
        int acc = 0;
        for (int i = 0; i < SCAN_NBLK; i++) {
            int t = g_bsum[i];
            g_bsum[i] = acc;
            acc += t;
        }
    }
}

__global__ void k_scanC() {
    int i = blockIdx.x * blockDim.x + threadIdx.x;
    if (i < 2 * NN) g_offs[i] += g_bsum[i / SCAN_ELEMS];
    if (i == 0) g_offs[2 * NN] = 2 * NE;
}

__global__ void k_inv() {
    int i = blockIdx.x * blockDim.x + threadIdx.x;
    if (i < NN) {
        int d = g_cnt[i];
        int b = g_cnt[NN + i];
        g_dinv[i] = d > 0 ? 1.0f / (float)d : 0.0f;
        g_binv[i] = b > 0 ? 1.0f / (float)b : 0.0f;
    }
}

// ---- CSR fill: consumes g_cnt as cursors via atomicSub ----
__global__ void k_fill() {
    int i = blockIdx.x * blockDim.x + threadIdx.x;
    if (i >= NE) return;
    int n = g_ni[i];
    int e = g_ei[i];
    int pn = g_offs[n] + atomicSub(&g_cnt[n], 1) - 1;
    g_csr[pn] = e;
    int pe = g_offs[NN + e] + atomicSub(&g_cnt[NN + e], 1) - 1;
    g_csr[pe] = n;
}

// ---- GEMM: C[M,128] = A[M,128] @ W[128,128] ----
__global__ __launch_bounds__(256) void k_gemm(const float* __restrict__ A,
                                              const float* __restrict__ W,
                                              float* __restrict__ C, int M) {
    __shared__ float sAT[32][129];
    __shared__ float sW[32][128];
    int tid = threadIdx.x;
    int tx = tid & 15;
    int ty = tid >> 4;
    int rb = blockIdx.x * 128;
    int lr = tid >> 3;
    int kq = tid & 7;

    float acc[8][8];
#pragma unroll
    for (int i = 0; i < 8; i++)
#pragma unroll
        for (int j = 0; j < 8; j++) acc[i][j] = 0.0f;

    for (int kk = 0; kk < 128; kk += 32) {
        __syncthreads();
#pragma unroll
        for (int t = 0; t < 4; t++) {
            int r = lr + t * 32;
            float4 v = make_float4(0.f, 0.f, 0.f, 0.f);
            if (rb + r < M)
                v = *(const float4*)(A + (size_t)(rb + r) * HID + kk + kq * 4);
            sAT[kq * 4 + 0][r] = v.x;
            sAT[kq * 4 + 1][r] = v.y;
            sAT[kq * 4 + 2][r] = v.z;
            sAT[kq * 4 + 3][r] = v.w;
        }
#pragma unroll
        for (int t = 0; t < 4; t++) {
            int i4 = tid + t * 256;
            int k = i4 >> 5, c4 = i4 & 31;
            *(float4*)(&sW[k][c4 * 4]) =
                *(const float4*)(W + (size_t)(kk + k) * HID + c4 * 4);
        }
        __syncthreads();

#pragma unroll
        for (int k = 0; k < 32; k++) {
            float a[8], b[8];
#pragma unroll
            for (int i = 0; i < 8; i++) a[i] = sAT[k][ty * 8 + i];
            *(float4*)(b)     = *(const float4*)(&sW[k][tx * 8]);
            *(float4*)(b + 4) = *(const float4*)(&sW[k][tx * 8 + 4]);
#pragma unroll
            for (int i = 0; i < 8; i++)
#pragma unroll
                for (int j = 0; j < 8; j++) acc[i][j] += a[i] * b[j];
        }
    }

#pragma unroll
    for (int i = 0; i < 8; i++) {
        int r = rb + ty * 8 + i;
        if (r < M) {
            *(float4*)(C + (size_t)r * HID + tx * 8)     = *(float4*)(&acc[i][0]);
            *(float4*)(C + (size_t)r * HID + tx * 8 + 4) = *(float4*)(&acc[i][4]);
        }
    }
}

// ---- edge gather: m[e] = binv[e] * sum_{n in edge e} xw[n]   (warp per edge) ----
__global__ __launch_bounds__(256) void k_gather_e(const float* __restrict__ src,
                                                  float* __restrict__ dst) {
    int g = blockIdx.x * blockDim.x + threadIdx.x;
    int e = g >> 5;
    int lane = g & 31;
    if (e >= NN) return;
    int beg = g_offs[NN + e];
    int end = g_offs[NN + e + 1];
    float4 acc = make_float4(0.f, 0.f, 0.f, 0.f);
    int j = beg;
    for (; j + 1 < end; j += 2) {
        int n0 = g_csr[j];
        int n1 = g_csr[j + 1];
        float4 v0 = ((const float4*)src)[(size_t)n0 * 32 + lane];
        float4 v1 = ((const float4*)src)[(size_t)n1 * 32 + lane];
        acc.x += v0.x + v1.x;
        acc.y += v0.y + v1.y;
        acc.z += v0.z + v1.z;
        acc.w += v0.w + v1.w;
    }
    if (j < end) {
        int n0 = g_csr[j];
        float4 v0 = ((const float4*)src)[(size_t)n0 * 32 + lane];
        acc.x += v0.x; acc.y += v0.y; acc.z += v0.z; acc.w += v0.w;
    }
    float s = g_binv[e];
    acc.x *= s; acc.y *= s; acc.z *= s; acc.w *= s;
    ((float4*)dst)[(size_t)e * 32 + lane] = acc;
}

// ---- node gather: out[n] = prelu(dinv[n] * sum_{e ∋ n} m[e] + bias [+ xres]) ----
template <bool RES>
__global__ __launch_bounds__(256) void k_gather_n(const float* __restrict__ src,
                                                  const float* __restrict__ bias,
                                                  const float* __restrict__ pa,
                                                  const float* __restrict__ xres,
                                                  float* __restrict__ dst) {
    int g = blockIdx.x * blockDim.x + threadIdx.x;
    int n = g >> 5;
    int lane = g & 31;
    if (n >= NN) return;
    int beg = g_offs[n];
    int end = g_offs[n + 1];
    float4 acc = make_float4(0.f, 0.f, 0.f, 0.f);
    int j = beg;
    for (; j + 1 < end; j += 2) {
        int e0 = g_csr[j];
        int e1 = g_csr[j + 1];
        float4 v0 = ((const float4*)src)[(size_t)e0 * 32 + lane];
        float4 v1 = ((const float4*)src)[(size_t)e1 * 32 + lane];
        acc.x += v0.x + v1.x;
        acc.y += v0.y + v1.y;
        acc.z += v0.z + v1.z;
        acc.w += v0.w + v1.w;
    }
    if (j < end) {
        int e0 = g_csr[j];
        float4 v0 = ((const float4*)src)[(size_t)e0 * 32 + lane];
        acc.x += v0.x; acc.y += v0.y; acc.z += v0.z; acc.w += v0.w;
    }
    float d = g_dinv[n];
    float a = pa[0];
    float4 b = ((const float4*)bias)[lane];
    acc.x = acc.x * d + b.x;
    acc.y = acc.y * d + b.y;
    acc.z = acc.z * d + b.z;
    acc.w = acc.w * d + b.w;
    if (RES) {
        float4 xv = ((const float4*)xres)[(size_t)n * 32 + lane];
        acc.x += xv.x; acc.y += xv.y; acc.z += xv.z; acc.w += xv.w;
    }
    acc.x = acc.x >= 0.f ? acc.x : a * acc.x;
    acc.y = acc.y >= 0.f ? acc.y : a * acc.y;
    acc.z = acc.z >= 0.f ? acc.z : a * acc.z;
    acc.w = acc.w >= 0.f ? acc.w : a * acc.w;
    ((float4*)dst)[(size_t)n * 32 + lane] = acc;
}

extern "C" void kernel_launch(void* const* d_in, const int* in_sizes, int n_in,
                              void* d_out, int out_size) {
    (void)in_sizes; (void)n_in; (void)out_size;
    const float* x   = (const float*)d_in[0];
    const void*  hei = d_in[1];
    const float* W1  = (const float*)d_in[2];
    const float* b1  = (const float*)d_in[3];
    const float* W2  = (const float*)d_in[4];
    const float* b2  = (const float*)d_in[5];
    const float* pa  = (const float*)d_in[6];
    float* out = (float*)d_out;

    float *pxw, *pm, *ph;
    cudaGetSymbolAddress((void**)&pxw, g_xw);
    cudaGetSymbolAddress((void**)&pm,  g_m);
    cudaGetSymbolAddress((void**)&ph,  g_h);

    const int GW_BLOCKS = (NN * 32) / 256;  // 6250: warp-per-segment grids

    // prep: dtype probe, counts, scan, inverses, CSR fill
    k_zero_flag<<<1, 32>>>();
    k_detect<<<16, 256>>>((const long long*)hei);
    k_zero_counts<<<(2 * NN + 255) / 256, 256>>>();
    k_idx_deg<<<(NE + 255) / 256, 256>>>(hei);
    k_scanA<<<SCAN_NBLK, SCAN_BS>>>();
    k_scanB<<<1, 32>>>();
    k_scanC<<<(2 * NN + 255) / 256, 256>>>();
    k_inv<<<(NN + 255) / 256, 256>>>();
    k_fill<<<(NE + 255) / 256, 256>>>();

    // ---- layer 1 ----
    k_gemm<<<(NN + 127) / 128, 256>>>(x, W1, pxw, NN);
    k_gather_e<<<GW_BLOCKS, 256>>>(pxw, pm);
    k_gather_n<false><<<GW_BLOCKS, 256>>>(pm, b1, pa, nullptr, ph);

    // ---- layer 2 ----
    k_gemm<<<(NN + 127) / 128, 256>>>(ph, W2, pxw, NN);
    k_gather_e<<<GW_BLOCKS, 256>>>(pxw, pm);
    k_gather_n<true><<<GW_BLOCKS, 256>>>(pm, b2, pa, x, out);
}

// round 4
// speedup vs baseline: 1.8262x; 1.0957x over previous
#include <cuda_runtime.h>

#define NN 50000
#define NE 600000
#define HID 128

#define SCAN_BS 256
#define SCAN_VT 8
#define SCAN_ELEMS (SCAN_BS * SCAN_VT)              // 2048
#define SCAN_NBLK ((2 * NN + SCAN_ELEMS - 1) / SCAN_ELEMS)  // 49

typedef unsigned long long u64;

// ---- scratch (static device allocations; no cudaMalloc allowed) ----
__device__ int   g_ni[NE];
__device__ int   g_ei[NE];
__device__ int   g_cnt[2 * NN];       // [0,NN): node degree D; [NN,2NN): hedge degree B
__device__ int   g_offs[2 * NN + 1];  // combined exclusive offsets
__device__ int   g_bsum[64];
__device__ int   g_csr[2 * NE];       // node rows hold edge ids; edge rows hold node ids
__device__ float g_dinv[NN];
__device__ float g_binv[NN];
__device__ float g_xw[NN * HID];
__device__ float g_m[NN * HID];
__device__ float g_h[NN * HID];
__device__ int   g_is_i32;

// ---- packed f32x2 helpers ----
__device__ __forceinline__ u64 ffma2(u64 a, u64 b, u64 c) {
    u64 d;
    asm("fma.rn.f32x2 %0, %1, %2, %3;" : "=l"(d) : "l"(a), "l"(b), "l"(c));
    return d;
}
__device__ __forceinline__ u64 dup2(float x) {
    u64 d;
    asm("mov.b64 %0, {%1, %1};" : "=l"(d) : "f"(x));
    return d;
}

// ---- dtype probe ----
__global__ void k_zero_flag() { if (threadIdx.x == 0 && blockIdx.x == 0) g_is_i32 = 0; }

__global__ void k_detect(const long long* __restrict__ hei64) {
    int i = blockIdx.x * blockDim.x + threadIdx.x;
    if (i < 4096) {
        long long v = hei64[i];
        if (v < 0 || v >= NN) atomicExch(&g_is_i32, 1);
    }
}

__global__ void k_idx_deg(const void* __restrict__ hei) {
    int i = blockIdx.x * blockDim.x + threadIdx.x;
    if (i >= NE) return;
    int n, e;
    if (g_is_i32) {
        const int* h32 = (const int*)hei;
        n = h32[i];
        e = h32[NE + i];
    } else {
        const long long* h64 = (const long long*)hei;
        n = (int)h64[i];
        e = (int)h64[NE + i];
    }
    if (n < 0 || n >= NN) n = 0;
    if (e < 0 || e >= NN) e = 0;
    g_ni[i] = n;
    g_ei[i] = e;
    atomicAdd(&g_cnt[n], 1);
    atomicAdd(&g_cnt[NN + e], 1);
}

// ---- exclusive scan over g_cnt[0 : 2NN] -> g_offs ----
__global__ __launch_bounds__(SCAN_BS) void k_scanA() {
    __shared__ int s[SCAN_BS];
    int blk = blockIdx.x, tid = threadIdx.x;
    int base = blk * SCAN_ELEMS + tid * SCAN_VT;
    int v[SCAN_VT];
    int sum = 0;
#pragma unroll
    for (int t = 0; t < SCAN_VT; t++) {
        v[t] = (base + t < 2 * NN) ? g_cnt[base + t] : 0;
        sum += v[t];
    }
    s[tid] = sum;
    __syncthreads();
    for (int off = 1; off < SCAN_BS; off <<= 1) {
        int t = (tid >= off) ? s[tid - off] : 0;
        __syncthreads();
        s[tid] += t;
        __syncthreads();
    }
    if (tid == SCAN_BS - 1) g_bsum[blk] = s[tid];
    int run = s[tid] - sum;
#pragma unroll
    for (int t = 0; t < SCAN_VT; t++) {
        if (base + t < 2 * NN) g_offs[base + t] = run;
        run += v[t];
    }
}

__global__ void k_scanB() {
    __shared__ int sh[64];
    int tid = threadIdx.x;
    int v = (tid < SCAN_NBLK) ? g_bsum[tid] : 0;
    sh[tid] = v;
    __syncthreads();
    for (int off = 1; off < 64; off <<= 1) {
        int t = (tid >= off) ? sh[tid - off] : 0;
        __syncthreads();
        sh[tid] += t;
        __syncthreads();
    }
    if (tid < SCAN_NBLK) g_bsum[tid] = sh[tid] - v;  // exclusive
}

// ---- offsets finalize + inverse degrees (fused) ----
__global__ void k_scanC() {
    int i = blockIdx.x * blockDim.x + threadIdx.x;
    if (i < 2 * NN) {
        g_offs[i] += g_bsum[i / SCAN_ELEMS];
        int c = g_cnt[i];
        float inv = c > 0 ? 1.0f / (float)c : 0.0f;
        if (i < NN) g_dinv[i] = inv;
        else        g_binv[i - NN] = inv;
    }
    if (i == 0) g_offs[2 * NN] = 2 * NE;
}

// ---- CSR fill: consumes g_cnt as cursors via atomicSub ----
__global__ void k_fill() {
    int i = blockIdx.x * blockDim.x + threadIdx.x;
    if (i >= NE) return;
    int n = g_ni[i];
    int e = g_ei[i];
    int pn = g_offs[n] + atomicSub(&g_cnt[n], 1) - 1;
    g_csr[pn] = e;
    int pe = g_offs[NN + e] + atomicSub(&g_cnt[NN + e], 1) - 1;
    g_csr[pe] = n;
}

// ---- GEMM: C[M,128] = A[M,128] @ W[128,128], packed f32x2 FMA microkernel ----
__global__ __launch_bounds__(256) void k_gemm(const float* __restrict__ A,
                                              const float* __restrict__ W,
                                              float* __restrict__ C, int M) {
    __shared__ float sAT[32][129];
    __shared__ float sW[32][128];
    int tid = threadIdx.x;
    int tx = tid & 15;
    int ty = tid >> 4;
    int rb = blockIdx.x * 128;
    int lr = tid >> 3;
    int kq = tid & 7;

    u64 acc2[8][4];
#pragma unroll
    for (int i = 0; i < 8; i++)
#pragma unroll
        for (int j = 0; j < 4; j++) acc2[i][j] = 0ull;

    for (int kk = 0; kk < 128; kk += 32) {
        __syncthreads();
#pragma unroll
        for (int t = 0; t < 4; t++) {
            int r = lr + t * 32;
            float4 v = make_float4(0.f, 0.f, 0.f, 0.f);
            if (rb + r < M)
                v = *(const float4*)(A + (size_t)(rb + r) * HID + kk + kq * 4);
            sAT[kq * 4 + 0][r] = v.x;
            sAT[kq * 4 + 1][r] = v.y;
            sAT[kq * 4 + 2][r] = v.z;
            sAT[kq * 4 + 3][r] = v.w;
        }
#pragma unroll
        for (int t = 0; t < 4; t++) {
            int i4 = tid + t * 256;
            int k = i4 >> 5, c4 = i4 & 31;
            *(float4*)(&sW[k][c4 * 4]) =
                *(const float4*)(W + (size_t)(kk + k) * HID + c4 * 4);
        }
        __syncthreads();

#pragma unroll
        for (int k = 0; k < 32; k++) {
            float a[8];
#pragma unroll
            for (int i = 0; i < 8; i++) a[i] = sAT[k][ty * 8 + i];
            float4 b0 = *(const float4*)(&sW[k][tx * 8]);
            float4 b1 = *(const float4*)(&sW[k][tx * 8 + 4]);
            u64 bb[4];
            bb[0] = ((const u64*)&b0)[0];
            bb[1] = ((const u64*)&b0)[1];
            bb[2] = ((const u64*)&b1)[0];
            bb[3] = ((const u64*)&b1)[1];
#pragma unroll
            for (int i = 0; i < 8; i++) {
                u64 aa = dup2(a[i]);
#pragma unroll
                for (int j = 0; j < 4; j++)
                    acc2[i][j] = ffma2(aa, bb[j], acc2[i][j]);
            }
        }
    }

#pragma unroll
    for (int i = 0; i < 8; i++) {
        int r = rb + ty * 8 + i;
        if (r < M) {
            *(float4*)(C + (size_t)r * HID + tx * 8)     = *(float4*)(&acc2[i][0]);
            *(float4*)(C + (size_t)r * HID + tx * 8 + 4) = *(float4*)(&acc2[i][2]);
        }
    }
}

// ---- edge gather: m[e] = binv[e] * sum_{n in edge e} xw[n]   (warp per edge) ----
__global__ __launch_bounds__(256) void k_gather_e(const float* __restrict__ src,
                                                  float* __restrict__ dst) {
    int g = blockIdx.x * blockDim.x + threadIdx.x;
    int e = g >> 5;
    int lane = g & 31;
    if (e >= NN) return;
    int beg = g_offs[NN + e];
    int end = g_offs[NN + e + 1];
    float4 acc = make_float4(0.f, 0.f, 0.f, 0.f);
    int j = beg;
    for (; j + 1 < end; j += 2) {
        int n0 = g_csr[j];
        int n1 = g_csr[j + 1];
        float4 v0 = ((const float4*)src)[(size_t)n0 * 32 + lane];
        float4 v1 = ((const float4*)src)[(size_t)n1 * 32 + lane];
        acc.x += v0.x + v1.x;
        acc.y += v0.y + v1.y;
        acc.z += v0.z + v1.z;
        acc.w += v0.w + v1.w;
    }
    if (j < end) {
        int n0 = g_csr[j];
        float4 v0 = ((const float4*)src)[(size_t)n0 * 32 + lane];
        acc.x += v0.x; acc.y += v0.y; acc.z += v0.z; acc.w += v0.w;
    }
    float s = g_binv[e];
    acc.x *= s; acc.y *= s; acc.z *= s; acc.w *= s;
    ((float4*)dst)[(size_t)e * 32 + lane] = acc;
}

// ---- node gather: out[n] = prelu(dinv[n] * sum_{e ∋ n} m[e] + bias [+ xres]) ----
template <bool RES>
__global__ __launch_bounds__(256) void k_gather_n(const float* __restrict__ src,
                                                  const float* __restrict__ bias,
                                                  const float* __restrict__ pa,
                                                  const float* __restrict__ xres,
                                                  float* __restrict__ dst) {
    int g = blockIdx.x * blockDim.x + threadIdx.x;
    int n = g >> 5;
    int lane = g & 31;
    if (n >= NN) return;
    int beg = g_offs[n];
    int end = g_offs[n + 1];
    float4 acc = make_float4(0.f, 0.f, 0.f, 0.f);
    int j = beg;
    for (; j + 1 < end; j += 2) {
        int e0 = g_csr[j];
        int e1 = g_csr[j + 1];
        float4 v0 = ((const float4*)src)[(size_t)e0 * 32 + lane];
        float4 v1 = ((const float4*)src)[(size_t)e1 * 32 + lane];
        acc.x += v0.x + v1.x;
        acc.y += v0.y + v1.y;
        acc.z += v0.z + v1.z;
        acc.w += v0.w + v1.w;
    }
    if (j < end) {
        int e0 = g_csr[j];
        float4 v0 = ((const float4*)src)[(size_t)e0 * 32 + lane];
        acc.x += v0.x; acc.y += v0.y; acc.z += v0.z; acc.w += v0.w;
    }
    float d = g_dinv[n];
    float a = pa[0];
    float4 b = ((const float4*)bias)[lane];
    acc.x = acc.x * d + b.x;
    acc.y = acc.y * d + b.y;
    acc.z = acc.z * d + b.z;
    acc.w = acc.w * d + b.w;
    if (RES) {
        float4 xv = ((const float4*)xres)[(size_t)n * 32 + lane];
        acc.x += xv.x; acc.y += xv.y; acc.z += xv.z; acc.w += xv.w;
    }
    acc.x = acc.x >= 0.f ? acc.x : a * acc.x;
    acc.y = acc.y >= 0.f ? acc.y : a * acc.y;
    acc.z = acc.z >= 0.f ? acc.z : a * acc.z;
    acc.w = acc.w >= 0.f ? acc.w : a * acc.w;
    ((float4*)dst)[(size_t)n * 32 + lane] = acc;
}

extern "C" void kernel_launch(void* const* d_in, const int* in_sizes, int n_in,
                              void* d_out, int out_size) {
    (void)in_sizes; (void)n_in; (void)out_size;
    const float* x   = (const float*)d_in[0];
    const void*  hei = d_in[1];
    const float* W1  = (const float*)d_in[2];
    const float* b1  = (const float*)d_in[3];
    const float* W2  = (const float*)d_in[4];
    const float* b2  = (const float*)d_in[5];
    const float* pa  = (const float*)d_in[6];
    float* out = (float*)d_out;

    float *pxw, *pm, *ph;
    int* pcnt;
    cudaGetSymbolAddress((void**)&pxw, g_xw);
    cudaGetSymbolAddress((void**)&pm,  g_m);
    cudaGetSymbolAddress((void**)&ph,  g_h);
    cudaGetSymbolAddress((void**)&pcnt, g_cnt);

    const int GW_BLOCKS = (NN * 32) / 256;  // 6250: warp-per-segment grids

    // prep: dtype probe, counts, scan(+inv), CSR fill
    k_zero_flag<<<1, 32>>>();
    k_detect<<<16, 256>>>((const long long*)hei);
    cudaMemsetAsync(pcnt, 0, sizeof(int) * 2 * NN, 0);
    k_idx_deg<<<(NE + 255) / 256, 256>>>(hei);
    k_scanA<<<SCAN_NBLK, SCAN_BS>>>();
    k_scanB<<<1, 64>>>();
    k_scanC<<<(2 * NN + 255) / 256, 256>>>();
    k_fill<<<(NE + 255) / 256, 256>>>();

    // ---- layer 1 ----
    k_gemm<<<(NN + 127) / 128, 256>>>(x, W1, pxw, NN);
    k_gather_e<<<GW_BLOCKS, 256>>>(pxw, pm);
    k_gather_n<false><<<GW_BLOCKS, 256>>>(pm, b1, pa, nullptr, ph);

    // ---- layer 2 ----
    k_gemm<<<(NN + 127) / 128, 256>>>(ph, W2, pxw, NN);
    k_gather_e<<<GW_BLOCKS, 256>>>(pxw, pm);
    k_gather_n<true><<<GW_BLOCKS, 256>>>(pm, b2, pa, x, out);
}